// round 1
// baseline (speedup 1.0000x reference)
#include <cuda_runtime.h>
#include <cuda_bf16.h>
#include <math.h>

// Problem constants
#define BATCH 256
#define CC    256          // channels
#define MM    196          // H*W = 14*14
#define DTRI  32896        // C*(C+1)/2
#define MAT   (CC*CC)      // 65536

// Scratch: 4 ping-pong matrices [B, C, C] fp32 (64 MB each), row sums, traces.
__device__ float g_P[(size_t)BATCH * MAT];
__device__ float g_Q[(size_t)BATCH * MAT];
__device__ float g_R[(size_t)BATCH * MAT];
__device__ float g_S[(size_t)BATCH * MAT];
__device__ float g_sums[BATCH * CC];
__device__ float g_norm[BATCH];

#define KT 16

// ---------------------------------------------------------------------------
// Row sums over spatial dim: s[b,c] = sum_m x[b,c,m]
// ---------------------------------------------------------------------------
__global__ void rowsum_kernel(const float* __restrict__ x, float* __restrict__ s) {
    int b = blockIdx.x;
    int c = threadIdx.x;
    const float* p = x + ((size_t)b * CC + c) * MM;
    float acc = 0.f;
#pragma unroll 7
    for (int m = 0; m < MM; ++m) acc += p[m];
    s[b * CC + c] = acc;
}

// ---------------------------------------------------------------------------
// Covariance GEMM (NT): P[b,i,j] = (sum_m x_i x_j  -  s_i*s_j/M) / M
// 64x64 tile, 256 threads, 4x4 microtile.
// ---------------------------------------------------------------------------
__global__ __launch_bounds__(256)
void cov_gemm_kernel(const float* __restrict__ x, const float* __restrict__ s,
                     float* __restrict__ P) {
    const int b = blockIdx.z;
    const int row0 = blockIdx.y * 64;
    const int col0 = blockIdx.x * 64;
    const float* xb = x + (size_t)b * CC * MM;
    const float* sb = s + b * CC;
    float* Pb = P + (size_t)b * MAT;

    __shared__ __align__(16) float As[KT][68];
    __shared__ __align__(16) float Bs[KT][68];

    const int t  = threadIdx.x;
    const int tx = t & 15, ty = t >> 4;
    const int lk = t & 15, li = t >> 4;

    float acc[4][4] = {};

    for (int kk = 0; kk < MM; kk += KT) {
        int k = kk + lk;
        bool ok = (k < MM);
#pragma unroll
        for (int r = 0; r < 4; ++r) {
            float av = 0.f, bv = 0.f;
            if (ok) {
                av = xb[(row0 + li + 16 * r) * MM + k];
                bv = xb[(col0 + li + 16 * r) * MM + k];
            }
            As[lk][li + 16 * r] = av;
            Bs[lk][li + 16 * r] = bv;
        }
        __syncthreads();
#pragma unroll
        for (int k2 = 0; k2 < KT; ++k2) {
            float4 a  = *reinterpret_cast<const float4*>(&As[k2][ty * 4]);
            float4 bq = *reinterpret_cast<const float4*>(&Bs[k2][tx * 4]);
            float av[4] = {a.x, a.y, a.z, a.w};
            float bw[4] = {bq.x, bq.y, bq.z, bq.w};
#pragma unroll
            for (int i = 0; i < 4; ++i)
#pragma unroll
                for (int j = 0; j < 4; ++j)
                    acc[i][j] += av[i] * bw[j];
        }
        __syncthreads();
    }

    const float invM = 1.0f / (float)MM;
#pragma unroll
    for (int i = 0; i < 4; ++i) {
        int gi = row0 + ty * 4 + i;
        float si = sb[gi] * invM;
#pragma unroll
        for (int j = 0; j < 4; ++j) {
            int gj = col0 + tx * 4 + j;
            float v = (acc[i][j] - si * sb[gj]) * invM;
            Pb[gi * CC + gj] = v;
        }
    }
}

// ---------------------------------------------------------------------------
// Trace: norm[b] = sum_i P[b,i,i]
// ---------------------------------------------------------------------------
__global__ void trace_kernel(const float* __restrict__ P, float* __restrict__ norm) {
    int b = blockIdx.x;
    int i = threadIdx.x;
    float v = P[(size_t)b * MAT + i * (CC + 1)];
    __shared__ float sh[8];
#pragma unroll
    for (int o = 16; o > 0; o >>= 1) v += __shfl_down_sync(0xffffffffu, v, o);
    if ((i & 31) == 0) sh[i >> 5] = v;
    __syncthreads();
    if (i < 8) {
        float w = sh[i];
#pragma unroll
        for (int o = 4; o > 0; o >>= 1) w += __shfl_down_sync(0xffu, w, o);
        if (i == 0) norm[b] = w;
    }
}

// ---------------------------------------------------------------------------
// Elementwise: P <- P/norm[b];  Q <- 1.5*I - 0.5*(P/norm[b])
// ---------------------------------------------------------------------------
__global__ void hat_kernel(float* __restrict__ P, float* __restrict__ Q,
                           const float* __restrict__ norm) {
    int b = blockIdx.y;
    int i = blockIdx.x;
    int j = threadIdx.x;
    size_t idx = (size_t)b * MAT + i * CC + j;
    float inv = 1.0f / norm[b];
    float ph = P[idx] * inv;
    P[idx] = ph;
    Q[idx] = (i == j ? 1.5f : 0.0f) - 0.5f * ph;
}

// ---------------------------------------------------------------------------
// Batched NN GEMM, 256x256x256 per batch, 64x64 tile / 4x4 microtile.
// mode 0: out = A@B
// mode 1: out = 1.5*I - 0.5*(A@B)          (Newton-Schulz T matrix)
// mode 2: out = (A@B) * sqrt(norm[b])       (final rescale)
// ---------------------------------------------------------------------------
__global__ __launch_bounds__(256)
void gemm_nn_kernel(const float* __restrict__ A, const float* __restrict__ B,
                    float* __restrict__ C, int mode,
                    const float* __restrict__ norm) {
    const int b = blockIdx.z;
    const int row0 = blockIdx.y * 64;
    const int col0 = blockIdx.x * 64;
    const float* Ab = A + (size_t)b * MAT;
    const float* Bb = B + (size_t)b * MAT;
    float* Cb = C + (size_t)b * MAT;

    __shared__ __align__(16) float As[KT][68];
    __shared__ __align__(16) float Bs[KT][68];

    const int t  = threadIdx.x;
    const int tx = t & 15, ty = t >> 4;
    const int ak = t & 15, ai = t >> 4;   // A-load: k = ak, row = ai + 16r
    const int bj = t & 63, bk = t >> 6;   // B-load: col = bj, k = bk + 4r

    float acc[4][4] = {};

    for (int kk = 0; kk < CC; kk += KT) {
#pragma unroll
        for (int r = 0; r < 4; ++r) {
            As[ak][ai + 16 * r]  = Ab[(row0 + ai + 16 * r) * CC + kk + ak];
            Bs[bk + 4 * r][bj]   = Bb[(kk + bk + 4 * r) * CC + col0 + bj];
        }
        __syncthreads();
#pragma unroll
        for (int k = 0; k < KT; ++k) {
            float4 a  = *reinterpret_cast<const float4*>(&As[k][ty * 4]);
            float4 bq = *reinterpret_cast<const float4*>(&Bs[k][tx * 4]);
            float av[4] = {a.x, a.y, a.z, a.w};
            float bw[4] = {bq.x, bq.y, bq.z, bq.w};
#pragma unroll
            for (int i = 0; i < 4; ++i)
#pragma unroll
                for (int j = 0; j < 4; ++j)
                    acc[i][j] += av[i] * bw[j];
        }
        __syncthreads();
    }

    float scale = 1.0f;
    if (mode == 2) scale = sqrtf(norm[b]);

#pragma unroll
    for (int i = 0; i < 4; ++i) {
        int gi = row0 + ty * 4 + i;
#pragma unroll
        for (int j = 0; j < 4; ++j) {
            int gj = col0 + tx * 4 + j;
            float v = acc[i][j];
            if (mode == 1) v = (gi == gj ? 1.5f : 0.0f) - 0.5f * v;
            else           v *= scale;
            Cb[gi * CC + gj] = v;
        }
    }
}

// ---------------------------------------------------------------------------
// Triu extraction + FC:  out[b,k] = sum_{i<=j} Y[b,i,j] * w[k, t(i,j)] + bias[k]
// One block per batch, 256 threads; each thread covers one j per row.
// ---------------------------------------------------------------------------
__global__ __launch_bounds__(256)
void fc_kernel(const float* __restrict__ Y, const float* __restrict__ w,
               const float* __restrict__ bias, float* __restrict__ out) {
    int b = blockIdx.x;
    int t = threadIdx.x;
    const float* Yb = Y + (size_t)b * MAT;
    float a0 = 0.f, a1 = 0.f;
    int rowstart = 0;
    for (int i = 0; i < CC; ++i) {
        int j = i + t;
        if (j < CC) {
            float v = Yb[i * CC + j];
            int tt = rowstart + t;
            a0 += v * w[tt];
            a1 += v * w[DTRI + tt];
        }
        rowstart += CC - i;
    }
    __shared__ float s0[256];
    __shared__ float s1[256];
    s0[t] = a0; s1[t] = a1;
    __syncthreads();
    for (int off = 128; off > 0; off >>= 1) {
        if (t < off) { s0[t] += s0[t + off]; s1[t] += s1[t + off]; }
        __syncthreads();
    }
    if (t == 0) {
        out[b * 2 + 0] = s0[0] + bias[0];
        out[b * 2 + 1] = s1[0] + bias[1];
    }
}

// ---------------------------------------------------------------------------
// Launch: covpool -> trace -> hat -> 12 NS GEMMs (fused epilogues) -> triu+fc
// Buffer schedule (no output aliases its inputs):
//   P = cov; hat: P=Ahat, Q=ZY (=Z0); R = P@Q (=Y0)
//   it1: P=TI(Q@R); S=R@P; R=P@Q         -> Y=S, Z=R
//   it2: P=TI(R@S); Q=S@P; S=P@R         -> Y=Q, Z=S
//   it3: P=TI(S@Q); R=Q@P; Q=P@S         -> Y=R, Z=Q
//   fin: P=TI(Q@R); S=(R@P)*sqrt(norm)
// ---------------------------------------------------------------------------
extern "C" void kernel_launch(void* const* d_in, const int* in_sizes, int n_in,
                              void* d_out, int out_size) {
    const float* x    = (const float*)d_in[0];
    const float* fc_w = (const float*)d_in[1];
    const float* fc_b = (const float*)d_in[2];
    float* out        = (float*)d_out;

    float *P, *Q, *R, *S, *sums, *nrm;
    cudaGetSymbolAddress((void**)&P, g_P);
    cudaGetSymbolAddress((void**)&Q, g_Q);
    cudaGetSymbolAddress((void**)&R, g_R);
    cudaGetSymbolAddress((void**)&S, g_S);
    cudaGetSymbolAddress((void**)&sums, g_sums);
    cudaGetSymbolAddress((void**)&nrm, g_norm);

    dim3 gridG(CC / 64, CC / 64, BATCH);   // 4 x 4 x 256
    dim3 blkG(256);

    rowsum_kernel<<<BATCH, CC>>>(x, sums);
    cov_gemm_kernel<<<gridG, blkG>>>(x, sums, P);
    trace_kernel<<<BATCH, CC>>>(P, nrm);
    hat_kernel<<<dim3(CC, BATCH), CC>>>(P, Q, nrm);

    // Y0 = Ahat @ ZY
    gemm_nn_kernel<<<gridG, blkG>>>(P, Q, R, 0, nrm);

    // iter 1  (Y=R, Z=Q)
    gemm_nn_kernel<<<gridG, blkG>>>(Q, R, P, 1, nrm);   // P = T
    gemm_nn_kernel<<<gridG, blkG>>>(R, P, S, 0, nrm);   // S = Ynew
    gemm_nn_kernel<<<gridG, blkG>>>(P, Q, R, 0, nrm);   // R = Znew

    // iter 2  (Y=S, Z=R)
    gemm_nn_kernel<<<gridG, blkG>>>(R, S, P, 1, nrm);   // P = T
    gemm_nn_kernel<<<gridG, blkG>>>(S, P, Q, 0, nrm);   // Q = Ynew
    gemm_nn_kernel<<<gridG, blkG>>>(P, R, S, 0, nrm);   // S = Znew

    // iter 3  (Y=Q, Z=S)
    gemm_nn_kernel<<<gridG, blkG>>>(S, Q, P, 1, nrm);   // P = T
    gemm_nn_kernel<<<gridG, blkG>>>(Q, P, R, 0, nrm);   // R = Ynew
    gemm_nn_kernel<<<gridG, blkG>>>(P, S, Q, 0, nrm);   // Q = Znew

    // final  (Y=R, Z=Q)
    gemm_nn_kernel<<<gridG, blkG>>>(Q, R, P, 1, nrm);   // P = T
    gemm_nn_kernel<<<gridG, blkG>>>(R, P, S, 2, nrm);   // S = Y * sqrt(norm)

    fc_kernel<<<BATCH, 256>>>(S, fc_w, fc_b, out);
}

// round 3
// speedup vs baseline: 2.4291x; 2.4291x over previous
#include <cuda_runtime.h>
#include <cuda_bf16.h>
#include <math.h>
#include <stdint.h>

#define BATCH 256
#define CCH   256
#define MMSP  196
#define DTRI  32896
#define MAT   65536

// Scratch matrices [B, 256, 256] fp32
__device__ float g_P[(size_t)BATCH * MAT];
__device__ float g_Q[(size_t)BATCH * MAT];
__device__ float g_R[(size_t)BATCH * MAT];
__device__ float g_S[(size_t)BATCH * MAT];
__device__ float g_sums[BATCH * CCH];
__device__ float g_norm[BATCH];

// ---------------------------------------------------------------------------
// Helpers
// ---------------------------------------------------------------------------
__device__ __forceinline__ uint32_t smem_u32(const void* p) {
    uint32_t a;
    asm("{ .reg .u64 t; cvta.to.shared.u64 t, %1; cvt.u32.u64 %0, t; }" : "=r"(a) : "l"(p));
    return a;
}

__device__ __forceinline__ void ldsm4(uint32_t addr, uint32_t* r) {
    asm volatile("ldmatrix.sync.aligned.m8n8.x4.shared.b16 {%0,%1,%2,%3}, [%4];"
        : "=r"(r[0]), "=r"(r[1]), "=r"(r[2]), "=r"(r[3]) : "r"(addr));
}

__device__ __forceinline__ void mma_bf16(float* d, const uint32_t* a,
                                         uint32_t b0, uint32_t b1) {
    asm volatile("mma.sync.aligned.m16n8k16.row.col.f32.bf16.bf16.f32 "
                 "{%0,%1,%2,%3}, {%4,%5,%6,%7}, {%8,%9}, {%0,%1,%2,%3};"
        : "+f"(d[0]), "+f"(d[1]), "+f"(d[2]), "+f"(d[3])
        : "r"(a[0]), "r"(a[1]), "r"(a[2]), "r"(a[3]), "r"(b0), "r"(b1));
}

__device__ __forceinline__ uint32_t pack2(float x, float y) {
    __nv_bfloat162 v = __floats2bfloat162_rn(x, y);
    return *reinterpret_cast<uint32_t*>(&v);
}

// Split float4 into bf16 hi (2 packed regs) and lo (2 packed regs)
__device__ __forceinline__ void split4(float4 v, uint32_t& h0, uint32_t& h1,
                                       uint32_t& l0, uint32_t& l1) {
    float hx = __bfloat162float(__float2bfloat16(v.x));
    float hy = __bfloat162float(__float2bfloat16(v.y));
    float hz = __bfloat162float(__float2bfloat16(v.z));
    float hw = __bfloat162float(__float2bfloat16(v.w));
    h0 = pack2(hx, hy); h1 = pack2(hz, hw);
    l0 = pack2(v.x - hx, v.y - hy);
    l1 = pack2(v.z - hz, v.w - hw);
}

// SMEM buffer geometry: per operand tile 128 rows x 128 bytes
//   row r: [ hi: 32 bf16 (chunks 0-3) | lo: 32 bf16 (chunks 4-7) ]
//   16B-chunk swizzle: stored chunk = logical_chunk ^ (r & 7)
#define ABUF(buf)   ((buf) * 32768)
#define BBUF(buf)   ((buf) * 32768 + 16384)
#define SMEM_TOTAL  65536

// ---------------------------------------------------------------------------
// Batched GEMM via mma.sync bf16 3-product split.
// C[b, m0:m0+128, n0:n0+128] = A[b] @ B[b]^T-ish: both operands stored row-major
// [dim][K] (valid because B is symmetric for NS stages, and cov uses x rows).
// modes: 0 plain; 1 C=1.5I-0.5*AB; 2 C=AB*sqrt(norm); 3 cov: C=Ahat, C2=ZY
// ---------------------------------------------------------------------------
__global__ __launch_bounds__(256)
void gemm_tc(const float* __restrict__ A, const float* __restrict__ B,
             float* __restrict__ C, float* __restrict__ C2,
             int lda, int ldb, long strA, long strB,
             int Klim, int mode,
             const float* __restrict__ norm, const float* __restrict__ sums) {
    extern __shared__ char smem[];
    const uint32_t smb = smem_u32(smem);

    const int tid  = threadIdx.x;
    const int wid  = tid >> 5;
    const int lane = tid & 31;
    const int wm = wid >> 2;        // 0..1  (m offset wm*64)
    const int wn = wid & 3;         // 0..3  (n offset wn*32)
    const int g  = lane >> 2;       // group id 0..7
    const int t  = lane & 3;        // thread-in-group

    const int bx = blockIdx.x;
    const int m0 = (bx >> 1) * 128;
    const int n0 = (bx & 1) * 128;
    const int b  = blockIdx.y;

    const float* Ab = A + (size_t)b * strA + (size_t)m0 * lda;
    const float* Bb = B + (size_t)b * strB + (size_t)n0 * ldb;

    float acc[4][4][4];
#pragma unroll
    for (int i = 0; i < 4; ++i)
#pragma unroll
        for (int j = 0; j < 4; ++j)
#pragma unroll
            for (int k = 0; k < 4; ++k) acc[i][j][k] = 0.f;

    const int nch = (Klim + 31) / 32;

    // per-thread load coords: idx = tid + i*256 -> row = idx>>3, quad = idx&7
    float4 va[4], vb[4];

    // ---- load chunk 0
#pragma unroll
    for (int i = 0; i < 4; ++i) {
        int idx = tid + i * 256, row = idx >> 3, q = idx & 7;
        int k0 = q * 4;
        if (k0 < Klim) {
            va[i] = *reinterpret_cast<const float4*>(Ab + (size_t)row * lda + k0);
            vb[i] = *reinterpret_cast<const float4*>(Bb + (size_t)row * ldb + k0);
        } else {
            va[i] = make_float4(0, 0, 0, 0); vb[i] = va[i];
        }
    }
    // ---- store chunk 0
#pragma unroll
    for (int i = 0; i < 4; ++i) {
        int idx = tid + i * 256, row = idx >> 3, q = idx & 7;
        uint32_t h0, h1, l0, l1;
        int swh = ((q >> 1) ^ (row & 7));
        int swl = ((4 + (q >> 1)) ^ (row & 7));
        split4(va[i], h0, h1, l0, l1);
        *reinterpret_cast<uint2*>(smem + ABUF(0) + row * 128 + swh * 16 + (q & 1) * 8) = make_uint2(h0, h1);
        *reinterpret_cast<uint2*>(smem + ABUF(0) + row * 128 + swl * 16 + (q & 1) * 8) = make_uint2(l0, l1);
        split4(vb[i], h0, h1, l0, l1);
        *reinterpret_cast<uint2*>(smem + BBUF(0) + row * 128 + swh * 16 + (q & 1) * 8) = make_uint2(h0, h1);
        *reinterpret_cast<uint2*>(smem + BBUF(0) + row * 128 + swl * 16 + (q & 1) * 8) = make_uint2(l0, l1);
    }
    __syncthreads();

    for (int ch = 0; ch < nch; ++ch) {
        const int buf = ch & 1;
        const uint32_t smA = smb + ABUF(buf);
        const uint32_t smB = smb + BBUF(buf);

        // prefetch next chunk to registers
        if (ch + 1 < nch) {
            int kbase = (ch + 1) * 32;
#pragma unroll
            for (int i = 0; i < 4; ++i) {
                int idx = tid + i * 256, row = idx >> 3, q = idx & 7;
                int k0 = kbase + q * 4;
                if (k0 < Klim) {
                    va[i] = *reinterpret_cast<const float4*>(Ab + (size_t)row * lda + k0);
                    vb[i] = *reinterpret_cast<const float4*>(Bb + (size_t)row * ldb + k0);
                } else {
                    va[i] = make_float4(0, 0, 0, 0); vb[i] = va[i];
                }
            }
        }

        // consume current chunk: 2 k-steps of 16
#pragma unroll
        for (int ks = 0; ks < 2; ++ks) {
            uint32_t ah[4][4], al[4][4];
#pragma unroll
            for (int mt = 0; mt < 4; ++mt) {
                int r = wm * 64 + mt * 16 + (lane & 15);
                int cbase = ks * 2 + (lane >> 4);
                uint32_t ahi = smA + r * 128 + (((cbase) ^ (r & 7)) << 4);
                uint32_t alo = smA + r * 128 + (((4 + cbase) ^ (r & 7)) << 4);
                ldsm4(ahi, ah[mt]);
                ldsm4(alo, al[mt]);
            }
            uint32_t bh[2][4], bl[2][4];
#pragma unroll
            for (int bt = 0; bt < 2; ++bt) {
                int r = wn * 32 + bt * 16 + ((lane >> 4) << 3) + (lane & 7);
                int cbase = ks * 2 + ((lane >> 3) & 1);
                uint32_t bhi = smB + r * 128 + (((cbase) ^ (r & 7)) << 4);
                uint32_t blo = smB + r * 128 + (((4 + cbase) ^ (r & 7)) << 4);
                ldsm4(bhi, bh[bt]);
                ldsm4(blo, bl[bt]);
            }
#pragma unroll
            for (int mt = 0; mt < 4; ++mt) {
#pragma unroll
                for (int nt = 0; nt < 4; ++nt) {
                    const uint32_t* bhp = &bh[nt >> 1][(nt & 1) * 2];
                    const uint32_t* blp = &bl[nt >> 1][(nt & 1) * 2];
                    mma_bf16(acc[mt][nt], ah[mt], bhp[0], bhp[1]);
                    mma_bf16(acc[mt][nt], ah[mt], blp[0], blp[1]);
                    mma_bf16(acc[mt][nt], al[mt], bhp[0], bhp[1]);
                }
            }
        }

        // store next chunk
        if (ch + 1 < nch) {
            const int nb = (ch + 1) & 1;
#pragma unroll
            for (int i = 0; i < 4; ++i) {
                int idx = tid + i * 256, row = idx >> 3, q = idx & 7;
                uint32_t h0, h1, l0, l1;
                int swh = ((q >> 1) ^ (row & 7));
                int swl = ((4 + (q >> 1)) ^ (row & 7));
                split4(va[i], h0, h1, l0, l1);
                *reinterpret_cast<uint2*>(smem + ABUF(nb) + row * 128 + swh * 16 + (q & 1) * 8) = make_uint2(h0, h1);
                *reinterpret_cast<uint2*>(smem + ABUF(nb) + row * 128 + swl * 16 + (q & 1) * 8) = make_uint2(l0, l1);
                split4(vb[i], h0, h1, l0, l1);
                *reinterpret_cast<uint2*>(smem + BBUF(nb) + row * 128 + swh * 16 + (q & 1) * 8) = make_uint2(h0, h1);
                *reinterpret_cast<uint2*>(smem + BBUF(nb) + row * 128 + swl * 16 + (q & 1) * 8) = make_uint2(l0, l1);
            }
        }
        __syncthreads();
    }

    // ---- epilogue
    float sc = 1.0f, invMn = 0.0f;
    const float* sb = 0;
    float* C2b = 0;
    if (mode == 2) sc = sqrtf(norm[b]);
    if (mode == 3) {
        invMn = 1.0f / (196.0f * norm[b]);
        sb = sums + b * CCH;
        C2b = C2 + (size_t)b * MAT;
    }
    float* Cb = C + (size_t)b * MAT;

#pragma unroll
    for (int mt = 0; mt < 4; ++mt) {
        int r0 = m0 + wm * 64 + mt * 16 + g;
#pragma unroll
        for (int nt = 0; nt < 4; ++nt) {
            int c0 = n0 + wn * 32 + nt * 8 + 2 * t;
            float* d = acc[mt][nt];
#pragma unroll
            for (int half = 0; half < 2; ++half) {
                int gi = r0 + half * 8;
                float v0 = d[half * 2 + 0];
                float v1 = d[half * 2 + 1];
                if (mode == 1) {
                    v0 = (gi == c0     ? 1.5f : 0.0f) - 0.5f * v0;
                    v1 = (gi == c0 + 1 ? 1.5f : 0.0f) - 0.5f * v1;
                } else if (mode == 2) {
                    v0 *= sc; v1 *= sc;
                } else if (mode == 3) {
                    float si = sb[gi] * (1.0f / 196.0f);
                    v0 = (v0 - si * sb[c0])     * invMn;
                    v1 = (v1 - si * sb[c0 + 1]) * invMn;
                    float w0 = (gi == c0     ? 1.5f : 0.0f) - 0.5f * v0;
                    float w1 = (gi == c0 + 1 ? 1.5f : 0.0f) - 0.5f * v1;
                    *reinterpret_cast<float2*>(C2b + (size_t)gi * CCH + c0) = make_float2(w0, w1);
                }
                *reinterpret_cast<float2*>(Cb + (size_t)gi * CCH + c0) = make_float2(v0, v1);
            }
        }
    }
}

// ---------------------------------------------------------------------------
// Row sums + trace(cov): s[b,c] = sum_m x, norm[b] = (sum q_i - sum s_i^2/M)/M
// ---------------------------------------------------------------------------
__global__ void rowsum_norm_kernel(const float* __restrict__ x,
                                   float* __restrict__ s, float* __restrict__ nrm) {
    int b = blockIdx.x, c = threadIdx.x;
    const float* p = x + ((size_t)b * CCH + c) * MMSP;
    float sum = 0.f, q = 0.f;
#pragma unroll 4
    for (int m = 0; m < MMSP; ++m) { float v = p[m]; sum += v; q += v * v; }
    s[b * CCH + c] = sum;
    float part = q - sum * sum * (1.0f / 196.0f);
    __shared__ float sh[8];
#pragma unroll
    for (int o = 16; o > 0; o >>= 1) part += __shfl_down_sync(0xffffffffu, part, o);
    if ((c & 31) == 0) sh[c >> 5] = part;
    __syncthreads();
    if (c < 8) {
        float w = sh[c];
#pragma unroll
        for (int o = 4; o > 0; o >>= 1) w += __shfl_down_sync(0xffu, w, o);
        if (c == 0) nrm[b] = w * (1.0f / 196.0f);
    }
}

// ---------------------------------------------------------------------------
// Triu + FC
// ---------------------------------------------------------------------------
__global__ __launch_bounds__(256)
void fc_kernel(const float* __restrict__ Y, const float* __restrict__ w,
               const float* __restrict__ bias, float* __restrict__ out) {
    int b = blockIdx.x;
    int t = threadIdx.x;
    const float* Yb = Y + (size_t)b * MAT;
    float a0 = 0.f, a1 = 0.f;
    int rowstart = 0;
    for (int i = 0; i < CCH; ++i) {
        int j = i + t;
        if (j < CCH) {
            float v = Yb[i * CCH + j];
            int tt = rowstart + t;
            a0 += v * w[tt];
            a1 += v * w[DTRI + tt];
        }
        rowstart += CCH - i;
    }
    __shared__ float s0[256];
    __shared__ float s1[256];
    s0[t] = a0; s1[t] = a1;
    __syncthreads();
    for (int off = 128; off > 0; off >>= 1) {
        if (t < off) { s0[t] += s0[t + off]; s1[t] += s1[t + off]; }
        __syncthreads();
    }
    if (t == 0) {
        out[b * 2 + 0] = s0[0] + bias[0];
        out[b * 2 + 1] = s1[0] + bias[1];
    }
}

// ---------------------------------------------------------------------------
// Launch
// ---------------------------------------------------------------------------
extern "C" void kernel_launch(void* const* d_in, const int* in_sizes, int n_in,
                              void* d_out, int out_size) {
    const float* x    = (const float*)d_in[0];
    const float* fc_w = (const float*)d_in[1];
    const float* fc_b = (const float*)d_in[2];
    float* out        = (float*)d_out;

    float *P, *Q, *R, *S, *sums, *nrm;
    cudaGetSymbolAddress((void**)&P, g_P);
    cudaGetSymbolAddress((void**)&Q, g_Q);
    cudaGetSymbolAddress((void**)&R, g_R);
    cudaGetSymbolAddress((void**)&S, g_S);
    cudaGetSymbolAddress((void**)&sums, g_sums);
    cudaGetSymbolAddress((void**)&nrm, g_norm);

    cudaFuncSetAttribute(gemm_tc, cudaFuncAttributeMaxDynamicSharedMemorySize, SMEM_TOTAL);

    dim3 gg(4, BATCH);

    rowsum_norm_kernel<<<BATCH, CCH>>>(x, sums, nrm);

    // cov + hat fused: P = Ahat, Q = ZY
    gemm_tc<<<gg, 256, SMEM_TOTAL>>>(x, x, P, Q, MMSP, MMSP,
                                     (long)CCH * MMSP, (long)CCH * MMSP,
                                     MMSP, 3, nrm, sums);
    // Y0 = Ahat @ ZY -> R
    gemm_tc<<<gg, 256, SMEM_TOTAL>>>(P, Q, R, 0, CCH, CCH, MAT, MAT, CCH, 0, nrm, 0);
    // iter 1 (Y=R, Z=Q)
    gemm_tc<<<gg, 256, SMEM_TOTAL>>>(Q, R, P, 0, CCH, CCH, MAT, MAT, CCH, 1, nrm, 0);
    gemm_tc<<<gg, 256, SMEM_TOTAL>>>(R, P, S, 0, CCH, CCH, MAT, MAT, CCH, 0, nrm, 0);
    gemm_tc<<<gg, 256, SMEM_TOTAL>>>(P, Q, R, 0, CCH, CCH, MAT, MAT, CCH, 0, nrm, 0);
    // iter 2 (Y=S, Z=R)
    gemm_tc<<<gg, 256, SMEM_TOTAL>>>(R, S, P, 0, CCH, CCH, MAT, MAT, CCH, 1, nrm, 0);
    gemm_tc<<<gg, 256, SMEM_TOTAL>>>(S, P, Q, 0, CCH, CCH, MAT, MAT, CCH, 0, nrm, 0);
    gemm_tc<<<gg, 256, SMEM_TOTAL>>>(P, R, S, 0, CCH, CCH, MAT, MAT, CCH, 0, nrm, 0);
    // iter 3 (Y=Q, Z=S)
    gemm_tc<<<gg, 256, SMEM_TOTAL>>>(S, Q, P, 0, CCH, CCH, MAT, MAT, CCH, 1, nrm, 0);
    gemm_tc<<<gg, 256, SMEM_TOTAL>>>(Q, P, R, 0, CCH, CCH, MAT, MAT, CCH, 0, nrm, 0);
    gemm_tc<<<gg, 256, SMEM_TOTAL>>>(P, S, Q, 0, CCH, CCH, MAT, MAT, CCH, 0, nrm, 0);
    // final (Y=R, Z=Q)
    gemm_tc<<<gg, 256, SMEM_TOTAL>>>(Q, R, P, 0, CCH, CCH, MAT, MAT, CCH, 1, nrm, 0);
    gemm_tc<<<gg, 256, SMEM_TOTAL>>>(R, P, S, 0, CCH, CCH, MAT, MAT, CCH, 2, nrm, 0);

    fc_kernel<<<BATCH, 256>>>(S, fc_w, fc_b, out);
}

// round 4
// speedup vs baseline: 2.8760x; 1.1840x over previous
#include <cuda_runtime.h>
#include <cuda_bf16.h>
#include <math.h>
#include <stdint.h>

#define BATCH 256
#define CCH   256
#define MMSP  196
#define KPAD  224
#define DTRI  32896
#define MAT   65536

// bf16 hi/lo planes for intermediates (each 32MB) + split input (29MB each)
__device__ __nv_bfloat16 g_Xhi[(size_t)BATCH * CCH * KPAD];
__device__ __nv_bfloat16 g_Xlo[(size_t)BATCH * CCH * KPAD];
__device__ __nv_bfloat16 g_Phi[(size_t)BATCH * MAT];
__device__ __nv_bfloat16 g_Plo[(size_t)BATCH * MAT];
__device__ __nv_bfloat16 g_Qhi[(size_t)BATCH * MAT];
__device__ __nv_bfloat16 g_Qlo[(size_t)BATCH * MAT];
__device__ __nv_bfloat16 g_Rhi[(size_t)BATCH * MAT];
__device__ __nv_bfloat16 g_Rlo[(size_t)BATCH * MAT];
__device__ __nv_bfloat16 g_Shi[(size_t)BATCH * MAT];
__device__ __nv_bfloat16 g_Slo[(size_t)BATCH * MAT];
__device__ float g_F[(size_t)BATCH * MAT];     // final Y * sqrt(norm), fp32
__device__ float g_sums[BATCH * CCH];
__device__ float g_norm[BATCH];

// ---------------------------------------------------------------------------
// Helpers
// ---------------------------------------------------------------------------
__device__ __forceinline__ uint32_t smem_u32(const void* p) {
    uint32_t a;
    asm("{ .reg .u64 t; cvta.to.shared.u64 t, %1; cvt.u32.u64 %0, t; }" : "=r"(a) : "l"(p));
    return a;
}
__device__ __forceinline__ void ldsm4(uint32_t addr, uint32_t* r) {
    asm volatile("ldmatrix.sync.aligned.m8n8.x4.shared.b16 {%0,%1,%2,%3}, [%4];"
        : "=r"(r[0]), "=r"(r[1]), "=r"(r[2]), "=r"(r[3]) : "r"(addr));
}
__device__ __forceinline__ void mma_bf16(float* d, const uint32_t* a,
                                         uint32_t b0, uint32_t b1) {
    asm volatile("mma.sync.aligned.m16n8k16.row.col.f32.bf16.bf16.f32 "
                 "{%0,%1,%2,%3}, {%4,%5,%6,%7}, {%8,%9}, {%0,%1,%2,%3};"
        : "+f"(d[0]), "+f"(d[1]), "+f"(d[2]), "+f"(d[3])
        : "r"(a[0]), "r"(a[1]), "r"(a[2]), "r"(a[3]), "r"(b0), "r"(b1));
}
__device__ __forceinline__ uint32_t pack2(float x, float y) {
    __nv_bfloat162 v = __floats2bfloat162_rn(x, y);
    return *reinterpret_cast<uint32_t*>(&v);
}
// hi/lo split of a float pair -> packed bf16x2 regs
__device__ __forceinline__ void split2(float v0, float v1, uint32_t& hi, uint32_t& lo) {
    float h0 = __bfloat162float(__float2bfloat16(v0));
    float h1 = __bfloat162float(__float2bfloat16(v1));
    hi = pack2(h0, h1);
    lo = pack2(v0 - h0, v1 - h1);
}
__device__ __forceinline__ void cp16(uint32_t dst, const void* src) {
    asm volatile("cp.async.cg.shared.global [%0], [%1], 16;" :: "r"(dst), "l"(src));
}
#define CP_COMMIT()  asm volatile("cp.async.commit_group;" ::: "memory")
#define CP_WAIT(N)   asm volatile("cp.async.wait_group %0;" :: "n"(N) : "memory")

// SMEM: buf b: A tile @ b*32768, B tile @ b*32768+16384.
// Tile = 128 rows x 128B. Row r: 16B chunks; logical chunk c stored at c^(r&7).
// Chunks 0-3 = hi (32 bf16), 4-7 = lo.
#define ABUF(b)   ((b) * 32768)
#define BBUF(b)   ((b) * 32768 + 16384)
#define SMEM_TOTAL 65536

// ---------------------------------------------------------------------------
// Batched GEMM on pre-split bf16 hi/lo planes; fp32 accum via 3-product split.
// modes: 0 C=AB -> planes; 1 C=1.5I-0.5AB -> planes;
//        2 Cf=AB*sqrt(norm) fp32; 3 cov: C=Ahat planes, C2=ZY planes
// ---------------------------------------------------------------------------
__global__ __launch_bounds__(256, 2)
void gemm_tc(const __nv_bfloat16* __restrict__ Ahi, const __nv_bfloat16* __restrict__ Alo,
             const __nv_bfloat16* __restrict__ Bhi, const __nv_bfloat16* __restrict__ Blo,
             __nv_bfloat16* __restrict__ Chi, __nv_bfloat16* __restrict__ Clo,
             __nv_bfloat16* __restrict__ C2hi, __nv_bfloat16* __restrict__ C2lo,
             float* __restrict__ Cf,
             int ldk, long strAB, int K, int mode,
             const float* __restrict__ norm, const float* __restrict__ sums) {
    extern __shared__ char smem[];
    const uint32_t smb = smem_u32(smem);

    const int tid  = threadIdx.x;
    const int wid  = tid >> 5;
    const int lane = tid & 31;
    const int wm = wid >> 2;
    const int wn = wid & 3;
    const int g  = lane >> 2;
    const int t  = lane & 3;

    const int bx = blockIdx.x;
    const int m0 = (bx >> 1) * 128;
    const int n0 = (bx & 1) * 128;
    const int b  = blockIdx.y;

    const __nv_bfloat16* Abh = Ahi + (size_t)b * strAB + (size_t)m0 * ldk;
    const __nv_bfloat16* Abl = Alo + (size_t)b * strAB + (size_t)m0 * ldk;
    const __nv_bfloat16* Bbh = Bhi + (size_t)b * strAB + (size_t)n0 * ldk;
    const __nv_bfloat16* Bbl = Blo + (size_t)b * strAB + (size_t)n0 * ldk;

    // per-thread cp.async coords: idx = tid + j*256 -> row = idx>>2, chunk c = idx&3
    const int r0c = (tid + 0)   >> 2, c0c = tid & 3;
    const int r1c = (tid + 256) >> 2;         // chunk id same (tid&3)

    const int nch = K >> 5;

    float acc[4][4][4];
#pragma unroll
    for (int i = 0; i < 4; ++i)
#pragma unroll
        for (int j = 0; j < 4; ++j)
#pragma unroll
            for (int k = 0; k < 4; ++k) acc[i][j][k] = 0.f;

    // issue chunk ch into buffer buf
    auto issue = [&](int ch, int buf) {
        int col = (ch << 5) + c0c * 8;
        uint32_t swh0 = (uint32_t)((c0c       ^ (r0c & 7)) << 4);
        uint32_t swl0 = (uint32_t)(((4 + c0c) ^ (r0c & 7)) << 4);
        uint32_t swh1 = (uint32_t)((c0c       ^ (r1c & 7)) << 4);
        uint32_t swl1 = (uint32_t)(((4 + c0c) ^ (r1c & 7)) << 4);
        uint32_t dA0 = smb + ABUF(buf) + r0c * 128;
        uint32_t dB0 = smb + BBUF(buf) + r0c * 128;
        uint32_t dA1 = smb + ABUF(buf) + r1c * 128;
        uint32_t dB1 = smb + BBUF(buf) + r1c * 128;
        cp16(dA0 + swh0, Abh + (size_t)r0c * ldk + col);
        cp16(dA0 + swl0, Abl + (size_t)r0c * ldk + col);
        cp16(dB0 + swh0, Bbh + (size_t)r0c * ldk + col);
        cp16(dB0 + swl0, Bbl + (size_t)r0c * ldk + col);
        cp16(dA1 + swh1, Abh + (size_t)r1c * ldk + col);
        cp16(dA1 + swl1, Abl + (size_t)r1c * ldk + col);
        cp16(dB1 + swh1, Bbh + (size_t)r1c * ldk + col);
        cp16(dB1 + swl1, Bbl + (size_t)r1c * ldk + col);
    };

    issue(0, 0); CP_COMMIT();
    if (nch > 1) { issue(1, 1); CP_COMMIT(); }

    for (int ch = 0; ch < nch; ++ch) {
        if (ch + 1 < nch) { CP_WAIT(1); } else { CP_WAIT(0); }
        __syncthreads();

        const int buf = ch & 1;
        const uint32_t smA = smb + ABUF(buf);
        const uint32_t smB = smb + BBUF(buf);

#pragma unroll
        for (int ks = 0; ks < 2; ++ks) {
            uint32_t ah[4][4], al[4][4];
#pragma unroll
            for (int mt = 0; mt < 4; ++mt) {
                int r = wm * 64 + mt * 16 + (lane & 15);
                int cb = ks * 2 + (lane >> 4);
                ldsm4(smA + r * 128 + ((cb       ^ (r & 7)) << 4), ah[mt]);
                ldsm4(smA + r * 128 + (((4 + cb) ^ (r & 7)) << 4), al[mt]);
            }
            uint32_t bh[2][4], bl[2][4];
#pragma unroll
            for (int bt = 0; bt < 2; ++bt) {
                int r = wn * 32 + bt * 16 + ((lane >> 4) << 3) + (lane & 7);
                int cb = ks * 2 + ((lane >> 3) & 1);
                ldsm4(smB + r * 128 + ((cb       ^ (r & 7)) << 4), bh[bt]);
                ldsm4(smB + r * 128 + (((4 + cb) ^ (r & 7)) << 4), bl[bt]);
            }
#pragma unroll
            for (int mt = 0; mt < 4; ++mt) {
#pragma unroll
                for (int nt = 0; nt < 4; ++nt) {
                    const uint32_t* bhp = &bh[nt >> 1][(nt & 1) * 2];
                    const uint32_t* blp = &bl[nt >> 1][(nt & 1) * 2];
                    mma_bf16(acc[mt][nt], ah[mt], bhp[0], bhp[1]);
                    mma_bf16(acc[mt][nt], ah[mt], blp[0], blp[1]);
                    mma_bf16(acc[mt][nt], al[mt], bhp[0], bhp[1]);
                }
            }
        }
        __syncthreads();
        if (ch + 2 < nch) { issue(ch + 2, buf); CP_COMMIT(); }
    }

    // ---- epilogue
    float sc = 1.0f, invMn = 0.0f;
    const float* sb = 0;
    if (mode == 2) sc = sqrtf(norm[b]);
    if (mode == 3) {
        invMn = 1.0f / (196.0f * norm[b]);
        sb = sums + b * CCH;
    }
    const size_t cbase = (size_t)b * MAT;

#pragma unroll
    for (int mt = 0; mt < 4; ++mt) {
        int r0 = m0 + wm * 64 + mt * 16 + g;
#pragma unroll
        for (int nt = 0; nt < 4; ++nt) {
            int c0 = n0 + wn * 32 + nt * 8 + 2 * t;
            float* d = acc[mt][nt];
#pragma unroll
            for (int half = 0; half < 2; ++half) {
                int gi = r0 + half * 8;
                float v0 = d[half * 2 + 0];
                float v1 = d[half * 2 + 1];
                size_t off = cbase + (size_t)gi * CCH + c0;
                if (mode == 2) {
                    *reinterpret_cast<float2*>(Cf + off) = make_float2(v0 * sc, v1 * sc);
                } else {
                    if (mode == 1) {
                        v0 = (gi == c0     ? 1.5f : 0.0f) - 0.5f * v0;
                        v1 = (gi == c0 + 1 ? 1.5f : 0.0f) - 0.5f * v1;
                    } else if (mode == 3) {
                        float si = sb[gi] * (1.0f / 196.0f);
                        v0 = (v0 - si * sb[c0])     * invMn;
                        v1 = (v1 - si * sb[c0 + 1]) * invMn;
                        float w0 = (gi == c0     ? 1.5f : 0.0f) - 0.5f * v0;
                        float w1 = (gi == c0 + 1 ? 1.5f : 0.0f) - 0.5f * v1;
                        uint32_t hi, lo;
                        split2(w0, w1, hi, lo);
                        *reinterpret_cast<uint32_t*>(C2hi + off) = hi;
                        *reinterpret_cast<uint32_t*>(C2lo + off) = lo;
                    }
                    uint32_t hi, lo;
                    split2(v0, v1, hi, lo);
                    *reinterpret_cast<uint32_t*>(Chi + off) = hi;
                    *reinterpret_cast<uint32_t*>(Clo + off) = lo;
                }
            }
        }
    }
}

// ---------------------------------------------------------------------------
// Split x into bf16 hi/lo planes, zero-padded K 196->224. One warp per row.
// ---------------------------------------------------------------------------
__global__ __launch_bounds__(256)
void split_x_kernel(const float* __restrict__ x,
                    __nv_bfloat16* __restrict__ xhi, __nv_bfloat16* __restrict__ xlo) {
    int row = blockIdx.x * 8 + (threadIdx.x >> 5);   // b*CCH + c
    int lane = threadIdx.x & 31;
    const float* src = x + (size_t)row * MMSP;
    __nv_bfloat16* dh = xhi + (size_t)row * KPAD;
    __nv_bfloat16* dl = xlo + (size_t)row * KPAD;
#pragma unroll
    for (int m = lane; m < KPAD; m += 32) {
        float v = (m < MMSP) ? src[m] : 0.f;
        __nv_bfloat16 h = __float2bfloat16(v);
        dh[m] = h;
        dl[m] = __float2bfloat16(v - __bfloat162float(h));
    }
}

// ---------------------------------------------------------------------------
// Row sums + trace(cov)
// ---------------------------------------------------------------------------
__global__ void rowsum_norm_kernel(const float* __restrict__ x,
                                   float* __restrict__ s, float* __restrict__ nrm) {
    int b = blockIdx.x, c = threadIdx.x;
    const float* p = x + ((size_t)b * CCH + c) * MMSP;
    float sum = 0.f, q = 0.f;
#pragma unroll 4
    for (int m = 0; m < MMSP; ++m) { float v = p[m]; sum += v; q += v * v; }
    s[b * CCH + c] = sum;
    float part = q - sum * sum * (1.0f / 196.0f);
    __shared__ float sh[8];
#pragma unroll
    for (int o = 16; o > 0; o >>= 1) part += __shfl_down_sync(0xffffffffu, part, o);
    if ((c & 31) == 0) sh[c >> 5] = part;
    __syncthreads();
    if (c < 8) {
        float w = sh[c];
#pragma unroll
        for (int o = 4; o > 0; o >>= 1) w += __shfl_down_sync(0xffu, w, o);
        if (c == 0) nrm[b] = w * (1.0f / 196.0f);
    }
}

// ---------------------------------------------------------------------------
// Triu + FC
// ---------------------------------------------------------------------------
__global__ __launch_bounds__(256)
void fc_kernel(const float* __restrict__ Y, const float* __restrict__ w,
               const float* __restrict__ bias, float* __restrict__ out) {
    int b = blockIdx.x;
    int t = threadIdx.x;
    const float* Yb = Y + (size_t)b * MAT;
    float a0 = 0.f, a1 = 0.f;
    int rowstart = 0;
    for (int i = 0; i < CCH; ++i) {
        int j = i + t;
        if (j < CCH) {
            float v = Yb[i * CCH + j];
            int tt = rowstart + t;
            a0 += v * w[tt];
            a1 += v * w[DTRI + tt];
        }
        rowstart += CCH - i;
    }
    __shared__ float s0[256];
    __shared__ float s1[256];
    s0[t] = a0; s1[t] = a1;
    __syncthreads();
    for (int off = 128; off > 0; off >>= 1) {
        if (t < off) { s0[t] += s0[t + off]; s1[t] += s1[t + off]; }
        __syncthreads();
    }
    if (t == 0) {
        out[b * 2 + 0] = s0[0] + bias[0];
        out[b * 2 + 1] = s1[0] + bias[1];
    }
}

// ---------------------------------------------------------------------------
// Launch
// ---------------------------------------------------------------------------
extern "C" void kernel_launch(void* const* d_in, const int* in_sizes, int n_in,
                              void* d_out, int out_size) {
    const float* x    = (const float*)d_in[0];
    const float* fc_w = (const float*)d_in[1];
    const float* fc_b = (const float*)d_in[2];
    float* out        = (float*)d_out;

    __nv_bfloat16 *Xh, *Xl, *Ph, *Pl, *Qh, *Ql, *Rh, *Rl, *Sh, *Sl;
    float *F, *sums, *nrm;
    cudaGetSymbolAddress((void**)&Xh, g_Xhi); cudaGetSymbolAddress((void**)&Xl, g_Xlo);
    cudaGetSymbolAddress((void**)&Ph, g_Phi); cudaGetSymbolAddress((void**)&Pl, g_Plo);
    cudaGetSymbolAddress((void**)&Qh, g_Qhi); cudaGetSymbolAddress((void**)&Ql, g_Qlo);
    cudaGetSymbolAddress((void**)&Rh, g_Rhi); cudaGetSymbolAddress((void**)&Rl, g_Rlo);
    cudaGetSymbolAddress((void**)&Sh, g_Shi); cudaGetSymbolAddress((void**)&Sl, g_Slo);
    cudaGetSymbolAddress((void**)&F, g_F);
    cudaGetSymbolAddress((void**)&sums, g_sums);
    cudaGetSymbolAddress((void**)&nrm, g_norm);

    cudaFuncSetAttribute(gemm_tc, cudaFuncAttributeMaxDynamicSharedMemorySize, SMEM_TOTAL);

    dim3 gg(4, BATCH);
    const long strX = (long)CCH * KPAD;
    const long strM = (long)MAT;

    rowsum_norm_kernel<<<BATCH, CCH>>>(x, sums, nrm);
    split_x_kernel<<<BATCH * CCH / 8, 256>>>(x, Xh, Xl);

    // cov+hat fused: P=Ahat, Q=ZY   (mode 3)
    gemm_tc<<<gg, 256, SMEM_TOTAL>>>(Xh, Xl, Xh, Xl, Ph, Pl, Qh, Ql, 0,
                                     KPAD, strX, KPAD, 3, nrm, sums);
    // R = Y0 = Ahat @ ZY
    gemm_tc<<<gg, 256, SMEM_TOTAL>>>(Ph, Pl, Qh, Ql, Rh, Rl, 0, 0, 0,
                                     CCH, strM, CCH, 0, nrm, 0);
    // iter1: S=T1=TI(Q@R); P=Y1=R@S; R=Z1=S@Q
    gemm_tc<<<gg, 256, SMEM_TOTAL>>>(Qh, Ql, Rh, Rl, Sh, Sl, 0, 0, 0, CCH, strM, CCH, 1, nrm, 0);
    gemm_tc<<<gg, 256, SMEM_TOTAL>>>(Rh, Rl, Sh, Sl, Ph, Pl, 0, 0, 0, CCH, strM, CCH, 0, nrm, 0);
    gemm_tc<<<gg, 256, SMEM_TOTAL>>>(Sh, Sl, Qh, Ql, Rh, Rl, 0, 0, 0, CCH, strM, CCH, 0, nrm, 0);
    // iter2: Q=T2=TI(R@P); S=Y2=P@Q; P=Z2=Q@R
    gemm_tc<<<gg, 256, SMEM_TOTAL>>>(Rh, Rl, Ph, Pl, Qh, Ql, 0, 0, 0, CCH, strM, CCH, 1, nrm, 0);
    gemm_tc<<<gg, 256, SMEM_TOTAL>>>(Ph, Pl, Qh, Ql, Sh, Sl, 0, 0, 0, CCH, strM, CCH, 0, nrm, 0);
    gemm_tc<<<gg, 256, SMEM_TOTAL>>>(Qh, Ql, Rh, Rl, Ph, Pl, 0, 0, 0, CCH, strM, CCH, 0, nrm, 0);
    // iter3: Q=T3=TI(P@S); R=Y3=S@Q; S=Z3=Q@P
    gemm_tc<<<gg, 256, SMEM_TOTAL>>>(Ph, Pl, Sh, Sl, Qh, Ql, 0, 0, 0, CCH, strM, CCH, 1, nrm, 0);
    gemm_tc<<<gg, 256, SMEM_TOTAL>>>(Sh, Sl, Qh, Ql, Rh, Rl, 0, 0, 0, CCH, strM, CCH, 0, nrm, 0);
    gemm_tc<<<gg, 256, SMEM_TOTAL>>>(Qh, Ql, Ph, Pl, Sh, Sl, 0, 0, 0, CCH, strM, CCH, 0, nrm, 0);
    // final: Q=T4=TI(S@R); F=(R@Q)*sqrt(norm)
    gemm_tc<<<gg, 256, SMEM_TOTAL>>>(Sh, Sl, Rh, Rl, Qh, Ql, 0, 0, 0, CCH, strM, CCH, 1, nrm, 0);
    gemm_tc<<<gg, 256, SMEM_TOTAL>>>(Rh, Rl, Qh, Ql, 0, 0, 0, 0, F,  CCH, strM, CCH, 2, nrm, 0);

    fc_kernel<<<BATCH, 256>>>(F, fc_w, fc_b, out);
}

// round 5
// speedup vs baseline: 3.0013x; 1.0436x over previous
#include <cuda_runtime.h>
#include <cuda_bf16.h>
#include <math.h>
#include <stdint.h>

#define BATCH 256
#define CCH   256
#define MMSP  196
#define KPAD  224
#define DTRI  32896
#define MAT   65536

// bf16 hi/lo planes
__device__ __nv_bfloat16 g_Xhi[(size_t)BATCH * CCH * KPAD];
__device__ __nv_bfloat16 g_Xlo[(size_t)BATCH * CCH * KPAD];
__device__ __nv_bfloat16 g_Phi[(size_t)BATCH * MAT];
__device__ __nv_bfloat16 g_Plo[(size_t)BATCH * MAT];
__device__ __nv_bfloat16 g_Qhi[(size_t)BATCH * MAT];
__device__ __nv_bfloat16 g_Qlo[(size_t)BATCH * MAT];
__device__ __nv_bfloat16 g_Rhi[(size_t)BATCH * MAT];
__device__ __nv_bfloat16 g_Rlo[(size_t)BATCH * MAT];
__device__ __nv_bfloat16 g_Shi[(size_t)BATCH * MAT];
__device__ __nv_bfloat16 g_Slo[(size_t)BATCH * MAT];
__device__ __nv_bfloat16 g_Thi[(size_t)BATCH * MAT];
__device__ __nv_bfloat16 g_Tlo[(size_t)BATCH * MAT];
__device__ float g_F[(size_t)BATCH * MAT];
__device__ float g_sums[BATCH * CCH];
__device__ float g_norm[BATCH];

// ---------------------------------------------------------------------------
__device__ __forceinline__ uint32_t smem_u32(const void* p) {
    uint32_t a;
    asm("{ .reg .u64 t; cvta.to.shared.u64 t, %1; cvt.u32.u64 %0, t; }" : "=r"(a) : "l"(p));
    return a;
}
__device__ __forceinline__ void ldsm4(uint32_t addr, uint32_t* r) {
    asm volatile("ldmatrix.sync.aligned.m8n8.x4.shared.b16 {%0,%1,%2,%3}, [%4];"
        : "=r"(r[0]), "=r"(r[1]), "=r"(r[2]), "=r"(r[3]) : "r"(addr));
}
__device__ __forceinline__ void mma_bf16(float* d, const uint32_t* a,
                                         uint32_t b0, uint32_t b1) {
    asm volatile("mma.sync.aligned.m16n8k16.row.col.f32.bf16.bf16.f32 "
                 "{%0,%1,%2,%3}, {%4,%5,%6,%7}, {%8,%9}, {%0,%1,%2,%3};"
        : "+f"(d[0]), "+f"(d[1]), "+f"(d[2]), "+f"(d[3])
        : "r"(a[0]), "r"(a[1]), "r"(a[2]), "r"(a[3]), "r"(b0), "r"(b1));
}
__device__ __forceinline__ uint32_t pack2(float x, float y) {
    __nv_bfloat162 v = __floats2bfloat162_rn(x, y);
    return *reinterpret_cast<uint32_t*>(&v);
}
__device__ __forceinline__ void split2(float v0, float v1, uint32_t& hi, uint32_t& lo) {
    float h0 = __bfloat162float(__float2bfloat16(v0));
    float h1 = __bfloat162float(__float2bfloat16(v1));
    hi = pack2(h0, h1);
    lo = pack2(v0 - h0, v1 - h1);
}
__device__ __forceinline__ void cp16(uint32_t dst, const void* src) {
    asm volatile("cp.async.cg.shared.global [%0], [%1], 16;" :: "r"(dst), "l"(src));
}
#define CP_COMMIT()  asm volatile("cp.async.commit_group;" ::: "memory")
#define CP_WAIT(N)   asm volatile("cp.async.wait_group %0;" :: "n"(N) : "memory")

// 3 buffers: buf b: A @ b*32768, B @ b*32768+16384. Row r of tile: 16B chunks,
// logical chunk c stored at (c ^ (r&7)); chunks 0-3 hi, 4-7 lo.
#define ABUF(b)   ((b) * 32768)
#define BBUF(b)   ((b) * 32768 + 16384)
#define SMEM_TOTAL (3 * 32768)

// ---------------------------------------------------------------------------
// Batched GEMM on pre-split bf16 hi/lo planes; fp32 accum, 3-product split.
// blockIdx.x in [0,4): set 1 with 'mode'; [4,8): set 2 (always mode 0).
// modes: 0 planes; 1 TI planes; 2 fp32*sqrt(norm); 3 cov (Ahat + ZY planes)
// ---------------------------------------------------------------------------
__global__ __launch_bounds__(256, 2)
void gemm_tc(const __nv_bfloat16* __restrict__ Ahi, const __nv_bfloat16* __restrict__ Alo,
             const __nv_bfloat16* __restrict__ Bhi, const __nv_bfloat16* __restrict__ Blo,
             __nv_bfloat16* __restrict__ Chi, __nv_bfloat16* __restrict__ Clo,
             __nv_bfloat16* __restrict__ C2hi, __nv_bfloat16* __restrict__ C2lo,
             float* __restrict__ Cf,
             const __nv_bfloat16* A2hi, const __nv_bfloat16* A2lo,
             const __nv_bfloat16* B2hi, const __nv_bfloat16* B2lo,
             __nv_bfloat16* D2hi, __nv_bfloat16* D2lo,
             int ldk, long strAB, int K, int mode,
             const float* __restrict__ norm, const float* __restrict__ sums) {
    extern __shared__ char smem[];
    const uint32_t smb = smem_u32(smem);

    const int tid  = threadIdx.x;
    const int wid  = tid >> 5;
    const int lane = tid & 31;
    const int wm = wid >> 2;
    const int wn = wid & 3;
    const int g  = lane >> 2;
    const int t  = lane & 3;

    int bx = blockIdx.x;
    const int b = blockIdx.y;

    const __nv_bfloat16 *pAh = Ahi, *pAl = Alo, *pBh = Bhi, *pBl = Blo;
    __nv_bfloat16 *pCh = Chi, *pCl = Clo;
    if (bx >= 4) {
        bx -= 4;
        pAh = A2hi; pAl = A2lo; pBh = B2hi; pBl = B2lo;
        pCh = D2hi; pCl = D2lo;
        mode = 0;
    }
    const int m0 = (bx >> 1) * 128;
    const int n0 = (bx & 1) * 128;

    const __nv_bfloat16* Abh = pAh + (size_t)b * strAB + (size_t)m0 * ldk;
    const __nv_bfloat16* Abl = pAl + (size_t)b * strAB + (size_t)m0 * ldk;
    const __nv_bfloat16* Bbh = pBh + (size_t)b * strAB + (size_t)n0 * ldk;
    const __nv_bfloat16* Bbl = pBl + (size_t)b * strAB + (size_t)n0 * ldk;

    const int r0c = (tid + 0)   >> 2, c0c = tid & 3;
    const int r1c = (tid + 256) >> 2;
    const int nch = K >> 5;

    float acc[4][4][4];
#pragma unroll
    for (int i = 0; i < 4; ++i)
#pragma unroll
        for (int j = 0; j < 4; ++j)
#pragma unroll
            for (int k = 0; k < 4; ++k) acc[i][j][k] = 0.f;

    auto issue = [&](int ch, int buf) {
        int col = (ch << 5) + c0c * 8;
        uint32_t swh0 = (uint32_t)((c0c       ^ (r0c & 7)) << 4);
        uint32_t swl0 = (uint32_t)(((4 + c0c) ^ (r0c & 7)) << 4);
        uint32_t swh1 = (uint32_t)((c0c       ^ (r1c & 7)) << 4);
        uint32_t swl1 = (uint32_t)(((4 + c0c) ^ (r1c & 7)) << 4);
        uint32_t dA0 = smb + ABUF(buf) + r0c * 128;
        uint32_t dB0 = smb + BBUF(buf) + r0c * 128;
        uint32_t dA1 = smb + ABUF(buf) + r1c * 128;
        uint32_t dB1 = smb + BBUF(buf) + r1c * 128;
        cp16(dA0 + swh0, Abh + (size_t)r0c * ldk + col);
        cp16(dA0 + swl0, Abl + (size_t)r0c * ldk + col);
        cp16(dB0 + swh0, Bbh + (size_t)r0c * ldk + col);
        cp16(dB0 + swl0, Bbl + (size_t)r0c * ldk + col);
        cp16(dA1 + swh1, Abh + (size_t)r1c * ldk + col);
        cp16(dA1 + swl1, Abl + (size_t)r1c * ldk + col);
        cp16(dB1 + swh1, Bbh + (size_t)r1c * ldk + col);
        cp16(dB1 + swl1, Bbl + (size_t)r1c * ldk + col);
    };

    issue(0, 0); CP_COMMIT();
    if (nch > 1) { issue(1, 1); CP_COMMIT(); }

    for (int ch = 0; ch < nch; ++ch) {
        if (ch + 1 < nch) { CP_WAIT(1); } else { CP_WAIT(0); }
        __syncthreads();

        // prefetch chunk ch+2 into buffer (ch+2)%3 (last read at ch-1, safe post-barrier)
        if (ch + 2 < nch) { issue(ch + 2, (ch + 2) % 3); CP_COMMIT(); }

        const int buf = ch % 3;
        const uint32_t smA = smb + ABUF(buf);
        const uint32_t smB = smb + BBUF(buf);

#pragma unroll
        for (int ks = 0; ks < 2; ++ks) {
            uint32_t ah[4][4], al[4][4];
#pragma unroll
            for (int mt = 0; mt < 4; ++mt) {
                int r = wm * 64 + mt * 16 + (lane & 15);
                int cb = ks * 2 + (lane >> 4);
                ldsm4(smA + r * 128 + ((cb       ^ (r & 7)) << 4), ah[mt]);
                ldsm4(smA + r * 128 + (((4 + cb) ^ (r & 7)) << 4), al[mt]);
            }
            uint32_t bh[2][4], bl[2][4];
#pragma unroll
            for (int bt = 0; bt < 2; ++bt) {
                int r = wn * 32 + bt * 16 + ((lane >> 4) << 3) + (lane & 7);
                int cb = ks * 2 + ((lane >> 3) & 1);
                ldsm4(smB + r * 128 + ((cb       ^ (r & 7)) << 4), bh[bt]);
                ldsm4(smB + r * 128 + (((4 + cb) ^ (r & 7)) << 4), bl[bt]);
            }
#pragma unroll
            for (int mt = 0; mt < 4; ++mt) {
#pragma unroll
                for (int nt = 0; nt < 4; ++nt) {
                    const uint32_t* bhp = &bh[nt >> 1][(nt & 1) * 2];
                    const uint32_t* blp = &bl[nt >> 1][(nt & 1) * 2];
                    mma_bf16(acc[mt][nt], ah[mt], bhp[0], bhp[1]);
                    mma_bf16(acc[mt][nt], ah[mt], blp[0], blp[1]);
                    mma_bf16(acc[mt][nt], al[mt], bhp[0], bhp[1]);
                }
            }
        }
    }

    // ---- epilogue
    float sc = 1.0f, invMn = 0.0f;
    const float* sb = 0;
    if (mode == 2) sc = sqrtf(norm[b]);
    if (mode == 3) {
        invMn = 1.0f / (196.0f * norm[b]);
        sb = sums + b * CCH;
    }
    const size_t cbase = (size_t)b * MAT;

#pragma unroll
    for (int mt = 0; mt < 4; ++mt) {
        int r0 = m0 + wm * 64 + mt * 16 + g;
#pragma unroll
        for (int nt = 0; nt < 4; ++nt) {
            int c0 = n0 + wn * 32 + nt * 8 + 2 * t;
            float* d = acc[mt][nt];
#pragma unroll
            for (int half = 0; half < 2; ++half) {
                int gi = r0 + half * 8;
                float v0 = d[half * 2 + 0];
                float v1 = d[half * 2 + 1];
                size_t off = cbase + (size_t)gi * CCH + c0;
                if (mode == 2) {
                    *reinterpret_cast<float2*>(Cf + off) = make_float2(v0 * sc, v1 * sc);
                } else {
                    if (mode == 1) {
                        v0 = (gi == c0     ? 1.5f : 0.0f) - 0.5f * v0;
                        v1 = (gi == c0 + 1 ? 1.5f : 0.0f) - 0.5f * v1;
                    } else if (mode == 3) {
                        float si = sb[gi] * (1.0f / 196.0f);
                        v0 = (v0 - si * sb[c0])     * invMn;
                        v1 = (v1 - si * sb[c0 + 1]) * invMn;
                        float w0 = (gi == c0     ? 1.5f : 0.0f) - 0.5f * v0;
                        float w1 = (gi == c0 + 1 ? 1.5f : 0.0f) - 0.5f * v1;
                        uint32_t hi2, lo2;
                        split2(w0, w1, hi2, lo2);
                        *reinterpret_cast<uint32_t*>(C2hi + off) = hi2;
                        *reinterpret_cast<uint32_t*>(C2lo + off) = lo2;
                    }
                    uint32_t hi, lo;
                    split2(v0, v1, hi, lo);
                    *reinterpret_cast<uint32_t*>(pCh + off) = hi;
                    *reinterpret_cast<uint32_t*>(pCl + off) = lo;
                }
            }
        }
    }
}

// ---------------------------------------------------------------------------
__global__ __launch_bounds__(256)
void split_x_kernel(const float* __restrict__ x,
                    __nv_bfloat16* __restrict__ xhi, __nv_bfloat16* __restrict__ xlo) {
    int row = blockIdx.x * 8 + (threadIdx.x >> 5);
    int lane = threadIdx.x & 31;
    const float* src = x + (size_t)row * MMSP;
    __nv_bfloat16* dh = xhi + (size_t)row * KPAD;
    __nv_bfloat16* dl = xlo + (size_t)row * KPAD;
#pragma unroll
    for (int m = lane; m < KPAD; m += 32) {
        float v = (m < MMSP) ? src[m] : 0.f;
        __nv_bfloat16 h = __float2bfloat16(v);
        dh[m] = h;
        dl[m] = __float2bfloat16(v - __bfloat162float(h));
    }
}

__global__ void rowsum_norm_kernel(const float* __restrict__ x,
                                   float* __restrict__ s, float* __restrict__ nrm) {
    int b = blockIdx.x, c = threadIdx.x;
    const float* p = x + ((size_t)b * CCH + c) * MMSP;
    float sum = 0.f, q = 0.f;
#pragma unroll 4
    for (int m = 0; m < MMSP; ++m) { float v = p[m]; sum += v; q += v * v; }
    s[b * CCH + c] = sum;
    float part = q - sum * sum * (1.0f / 196.0f);
    __shared__ float sh[8];
#pragma unroll
    for (int o = 16; o > 0; o >>= 1) part += __shfl_down_sync(0xffffffffu, part, o);
    if ((c & 31) == 0) sh[c >> 5] = part;
    __syncthreads();
    if (c < 8) {
        float w = sh[c];
#pragma unroll
        for (int o = 4; o > 0; o >>= 1) w += __shfl_down_sync(0xffu, w, o);
        if (c == 0) nrm[b] = w * (1.0f / 196.0f);
    }
}

__global__ __launch_bounds__(256)
void fc_kernel(const float* __restrict__ Y, const float* __restrict__ w,
               const float* __restrict__ bias, float* __restrict__ out) {
    int b = blockIdx.x;
    int t = threadIdx.x;
    const float* Yb = Y + (size_t)b * MAT;
    float a0 = 0.f, a1 = 0.f;
    int rowstart = 0;
    for (int i = 0; i < CCH; ++i) {
        int j = i + t;
        if (j < CCH) {
            float v = Yb[i * CCH + j];
            int tt = rowstart + t;
            a0 += v * w[tt];
            a1 += v * w[DTRI + tt];
        }
        rowstart += CCH - i;
    }
    __shared__ float s0[256];
    __shared__ float s1[256];
    s0[t] = a0; s1[t] = a1;
    __syncthreads();
    for (int off = 128; off > 0; off >>= 1) {
        if (t < off) { s0[t] += s0[t + off]; s1[t] += s1[t + off]; }
        __syncthreads();
    }
    if (t == 0) {
        out[b * 2 + 0] = s0[0] + bias[0];
        out[b * 2 + 1] = s1[0] + bias[1];
    }
}

// ---------------------------------------------------------------------------
extern "C" void kernel_launch(void* const* d_in, const int* in_sizes, int n_in,
                              void* d_out, int out_size) {
    const float* x    = (const float*)d_in[0];
    const float* fc_w = (const float*)d_in[1];
    const float* fc_b = (const float*)d_in[2];
    float* out        = (float*)d_out;

    __nv_bfloat16 *Xh, *Xl, *Ph, *Pl, *Qh, *Ql, *Rh, *Rl, *Sh, *Sl, *Th, *Tl;
    float *F, *sums, *nrm;
    cudaGetSymbolAddress((void**)&Xh, g_Xhi); cudaGetSymbolAddress((void**)&Xl, g_Xlo);
    cudaGetSymbolAddress((void**)&Ph, g_Phi); cudaGetSymbolAddress((void**)&Pl, g_Plo);
    cudaGetSymbolAddress((void**)&Qh, g_Qhi); cudaGetSymbolAddress((void**)&Ql, g_Qlo);
    cudaGetSymbolAddress((void**)&Rh, g_Rhi); cudaGetSymbolAddress((void**)&Rl, g_Rlo);
    cudaGetSymbolAddress((void**)&Sh, g_Shi); cudaGetSymbolAddress((void**)&Sl, g_Slo);
    cudaGetSymbolAddress((void**)&Th, g_Thi); cudaGetSymbolAddress((void**)&Tl, g_Tlo);
    cudaGetSymbolAddress((void**)&F, g_F);
    cudaGetSymbolAddress((void**)&sums, g_sums);
    cudaGetSymbolAddress((void**)&nrm, g_norm);

    cudaFuncSetAttribute(gemm_tc, cudaFuncAttributeMaxDynamicSharedMemorySize, SMEM_TOTAL);

    dim3 g1(4, BATCH);   // single GEMM
    dim3 g2(8, BATCH);   // fused pair
    const long strX = (long)CCH * KPAD;
    const long strM = (long)MAT;
    const __nv_bfloat16* nbp = 0;
    __nv_bfloat16* nbo = 0;

    rowsum_norm_kernel<<<BATCH, CCH>>>(x, sums, nrm);
    split_x_kernel<<<BATCH * CCH / 8, 256>>>(x, Xh, Xl);

    // cov+hat: P=Ahat, Q=ZY
    gemm_tc<<<g1, 256, SMEM_TOTAL>>>(Xh, Xl, Xh, Xl, Ph, Pl, Qh, Ql, (float*)0,
                                     nbp, nbp, nbp, nbp, nbo, nbo,
                                     KPAD, strX, KPAD, 3, nrm, sums);
    // Y0: R = P@Q
    gemm_tc<<<g1, 256, SMEM_TOTAL>>>(Ph, Pl, Qh, Ql, Rh, Rl, nbo, nbo, (float*)0,
                                     nbp, nbp, nbp, nbp, nbo, nbo,
                                     CCH, strM, CCH, 0, nrm, 0);
    // T1: S = TI(Q@R)                                    (Y=R, Z=Q)
    gemm_tc<<<g1, 256, SMEM_TOTAL>>>(Qh, Ql, Rh, Rl, Sh, Sl, nbo, nbo, (float*)0,
                                     nbp, nbp, nbp, nbp, nbo, nbo,
                                     CCH, strM, CCH, 1, nrm, 0);
    // pair1: T = R@S (Y1), P = S@Q (Z1)
    gemm_tc<<<g2, 256, SMEM_TOTAL>>>(Rh, Rl, Sh, Sl, Th, Tl, nbo, nbo, (float*)0,
                                     Sh, Sl, Qh, Ql, Ph, Pl,
                                     CCH, strM, CCH, 0, nrm, 0);
    // T2: S = TI(P@T)                                    (Y=T, Z=P)
    gemm_tc<<<g1, 256, SMEM_TOTAL>>>(Ph, Pl, Th, Tl, Sh, Sl, nbo, nbo, (float*)0,
                                     nbp, nbp, nbp, nbp, nbo, nbo,
                                     CCH, strM, CCH, 1, nrm, 0);
    // pair2: Q = T@S (Y2), R = S@P (Z2)
    gemm_tc<<<g2, 256, SMEM_TOTAL>>>(Th, Tl, Sh, Sl, Qh, Ql, nbo, nbo, (float*)0,
                                     Sh, Sl, Ph, Pl, Rh, Rl,
                                     CCH, strM, CCH, 0, nrm, 0);
    // T3: S = TI(R@Q)                                    (Y=Q, Z=R)
    gemm_tc<<<g1, 256, SMEM_TOTAL>>>(Rh, Rl, Qh, Ql, Sh, Sl, nbo, nbo, (float*)0,
                                     nbp, nbp, nbp, nbp, nbo, nbo,
                                     CCH, strM, CCH, 1, nrm, 0);
    // pair3: T = Q@S (Y3), P = S@R (Z3)
    gemm_tc<<<g2, 256, SMEM_TOTAL>>>(Qh, Ql, Sh, Sl, Th, Tl, nbo, nbo, (float*)0,
                                     Sh, Sl, Rh, Rl, Ph, Pl,
                                     CCH, strM, CCH, 0, nrm, 0);
    // T4: S = TI(P@T)                                    (Y=T, Z=P)
    gemm_tc<<<g1, 256, SMEM_TOTAL>>>(Ph, Pl, Th, Tl, Sh, Sl, nbo, nbo, (float*)0,
                                     nbp, nbp, nbp, nbp, nbo, nbo,
                                     CCH, strM, CCH, 1, nrm, 0);
    // final: F = (T@S) * sqrt(norm)
    gemm_tc<<<g1, 256, SMEM_TOTAL>>>(Th, Tl, Sh, Sl, nbo, nbo, nbo, nbo, F,
                                     nbp, nbp, nbp, nbp, nbo, nbo,
                                     CCH, strM, CCH, 2, nrm, 0);

    fc_kernel<<<BATCH, 256>>>(F, fc_w, fc_b, out);
}

// round 6
// speedup vs baseline: 3.2677x; 1.0887x over previous
#include <cuda_runtime.h>
#include <cuda_bf16.h>
#include <math.h>
#include <stdint.h>

#define BATCH 256
#define CCH   256
#define MMSP  196
#define KPAD  224
#define DTRI  32896
#define MAT   65536

// bf16 hi/lo planes
__device__ __nv_bfloat16 g_Xhi[(size_t)BATCH * CCH * KPAD];
__device__ __nv_bfloat16 g_Xlo[(size_t)BATCH * CCH * KPAD];
__device__ __nv_bfloat16 g_Phi[(size_t)BATCH * MAT];
__device__ __nv_bfloat16 g_Plo[(size_t)BATCH * MAT];
__device__ __nv_bfloat16 g_Qhi[(size_t)BATCH * MAT];
__device__ __nv_bfloat16 g_Qlo[(size_t)BATCH * MAT];
__device__ __nv_bfloat16 g_Rhi[(size_t)BATCH * MAT];
__device__ __nv_bfloat16 g_Rlo[(size_t)BATCH * MAT];
__device__ __nv_bfloat16 g_Shi[(size_t)BATCH * MAT];
__device__ __nv_bfloat16 g_Slo[(size_t)BATCH * MAT];
__device__ __nv_bfloat16 g_Thi[(size_t)BATCH * MAT];
__device__ __nv_bfloat16 g_Tlo[(size_t)BATCH * MAT];
__device__ float g_part[BATCH * 3 * 2];   // per-(batch, block) FC partials
__device__ float g_sums[BATCH * CCH];
__device__ float g_norm[BATCH];

// ---------------------------------------------------------------------------
__device__ __forceinline__ uint32_t smem_u32(const void* p) {
    uint32_t a;
    asm("{ .reg .u64 t; cvta.to.shared.u64 t, %1; cvt.u32.u64 %0, t; }" : "=r"(a) : "l"(p));
    return a;
}
__device__ __forceinline__ void ldsm4(uint32_t addr, uint32_t* r) {
    asm volatile("ldmatrix.sync.aligned.m8n8.x4.shared.b16 {%0,%1,%2,%3}, [%4];"
        : "=r"(r[0]), "=r"(r[1]), "=r"(r[2]), "=r"(r[3]) : "r"(addr));
}
__device__ __forceinline__ void mma_bf16(float* d, const uint32_t* a,
                                         uint32_t b0, uint32_t b1) {
    asm volatile("mma.sync.aligned.m16n8k16.row.col.f32.bf16.bf16.f32 "
                 "{%0,%1,%2,%3}, {%4,%5,%6,%7}, {%8,%9}, {%0,%1,%2,%3};"
        : "+f"(d[0]), "+f"(d[1]), "+f"(d[2]), "+f"(d[3])
        : "r"(a[0]), "r"(a[1]), "r"(a[2]), "r"(a[3]), "r"(b0), "r"(b1));
}
__device__ __forceinline__ void cp16(uint32_t dst, const void* src) {
    asm volatile("cp.async.cg.shared.global [%0], [%1], 16;" :: "r"(dst), "l"(src));
}
#define CP_COMMIT()  asm volatile("cp.async.commit_group;" ::: "memory")
#define CP_WAIT(N)   asm volatile("cp.async.wait_group %0;" :: "n"(N) : "memory")

#define ABUF(b)   ((b) * 32768)
#define BBUF(b)   ((b) * 32768 + 16384)
#define SMEM_TOTAL (3 * 32768)

// ---------------------------------------------------------------------------
// Symmetric-output batched GEMM on bf16 hi/lo planes, 3-product split.
// Blocks per matrix: bx=0 -> (0,0); 1 -> (0,128) (+ mirrored write); 2 -> (128,128).
// bx in [3,6): second GEMM of a fused pair (mode forced 0).
// modes: 0 planes; 1 TI planes; 2 fused triu-FC partials; 3 cov (Ahat + ZY)
// ---------------------------------------------------------------------------
__global__ __launch_bounds__(256, 2)
void gemm_tc(const __nv_bfloat16* __restrict__ Ahi, const __nv_bfloat16* __restrict__ Alo,
             const __nv_bfloat16* __restrict__ Bhi, const __nv_bfloat16* __restrict__ Blo,
             __nv_bfloat16* __restrict__ Chi, __nv_bfloat16* __restrict__ Clo,
             __nv_bfloat16* __restrict__ C2hi, __nv_bfloat16* __restrict__ C2lo,
             const __nv_bfloat16* A2hi, const __nv_bfloat16* A2lo,
             const __nv_bfloat16* B2hi, const __nv_bfloat16* B2lo,
             __nv_bfloat16* D2hi, __nv_bfloat16* D2lo,
             const float* __restrict__ fcw, float* __restrict__ part,
             int ldk, long strAB, int K, int mode,
             const float* __restrict__ norm, const float* __restrict__ sums) {
    extern __shared__ char smem[];
    const uint32_t smb = smem_u32(smem);

    const int tid  = threadIdx.x;
    const int wid  = tid >> 5;
    const int lane = tid & 31;
    const int wm = wid >> 2;
    const int wn = wid & 3;
    const int g  = lane >> 2;
    const int t  = lane & 3;

    int bx = blockIdx.x;
    const int b = blockIdx.y;

    const __nv_bfloat16 *pAh = Ahi, *pAl = Alo, *pBh = Bhi, *pBl = Blo;
    __nv_bfloat16 *pCh = Chi, *pCl = Clo;
    if (bx >= 3) {
        bx -= 3;
        pAh = A2hi; pAl = A2lo; pBh = B2hi; pBl = B2lo;
        pCh = D2hi; pCl = D2lo;
        mode = 0;
    }
    const int m0 = (bx == 2) ? 128 : 0;
    const int n0 = (bx >= 1) ? 128 : 0;
    const bool offdiag = (m0 != n0);

    const __nv_bfloat16* Abh = pAh + (size_t)b * strAB + (size_t)m0 * ldk;
    const __nv_bfloat16* Abl = pAl + (size_t)b * strAB + (size_t)m0 * ldk;
    const __nv_bfloat16* Bbh = pBh + (size_t)b * strAB + (size_t)n0 * ldk;
    const __nv_bfloat16* Bbl = pBl + (size_t)b * strAB + (size_t)n0 * ldk;

    const int r0c = (tid + 0)   >> 2, c0c = tid & 3;
    const int r1c = (tid + 256) >> 2;
    const int nch = K >> 5;

    float acc[4][4][4];
#pragma unroll
    for (int i = 0; i < 4; ++i)
#pragma unroll
        for (int j = 0; j < 4; ++j)
#pragma unroll
            for (int k = 0; k < 4; ++k) acc[i][j][k] = 0.f;

    auto issue = [&](int ch, int buf) {
        int col = (ch << 5) + c0c * 8;
        uint32_t swh0 = (uint32_t)((c0c       ^ (r0c & 7)) << 4);
        uint32_t swl0 = (uint32_t)(((4 + c0c) ^ (r0c & 7)) << 4);
        uint32_t swh1 = (uint32_t)((c0c       ^ (r1c & 7)) << 4);
        uint32_t swl1 = (uint32_t)(((4 + c0c) ^ (r1c & 7)) << 4);
        uint32_t dA0 = smb + ABUF(buf) + r0c * 128;
        uint32_t dB0 = smb + BBUF(buf) + r0c * 128;
        uint32_t dA1 = smb + ABUF(buf) + r1c * 128;
        uint32_t dB1 = smb + BBUF(buf) + r1c * 128;
        cp16(dA0 + swh0, Abh + (size_t)r0c * ldk + col);
        cp16(dA0 + swl0, Abl + (size_t)r0c * ldk + col);
        cp16(dB0 + swh0, Bbh + (size_t)r0c * ldk + col);
        cp16(dB0 + swl0, Bbl + (size_t)r0c * ldk + col);
        cp16(dA1 + swh1, Abh + (size_t)r1c * ldk + col);
        cp16(dA1 + swl1, Abl + (size_t)r1c * ldk + col);
        cp16(dB1 + swh1, Bbh + (size_t)r1c * ldk + col);
        cp16(dB1 + swl1, Bbl + (size_t)r1c * ldk + col);
    };

    issue(0, 0); CP_COMMIT();
    if (nch > 1) { issue(1, 1); CP_COMMIT(); }

    for (int ch = 0; ch < nch; ++ch) {
        if (ch + 1 < nch) { CP_WAIT(1); } else { CP_WAIT(0); }
        __syncthreads();
        if (ch + 2 < nch) { issue(ch + 2, (ch + 2) % 3); CP_COMMIT(); }

        const int buf = ch % 3;
        const uint32_t smA = smb + ABUF(buf);
        const uint32_t smB = smb + BBUF(buf);

#pragma unroll
        for (int ks = 0; ks < 2; ++ks) {
            uint32_t ah[4][4], al[4][4];
#pragma unroll
            for (int mt = 0; mt < 4; ++mt) {
                int r = wm * 64 + mt * 16 + (lane & 15);
                int cb = ks * 2 + (lane >> 4);
                ldsm4(smA + r * 128 + ((cb       ^ (r & 7)) << 4), ah[mt]);
                ldsm4(smA + r * 128 + (((4 + cb) ^ (r & 7)) << 4), al[mt]);
            }
            uint32_t bh[2][4], bl[2][4];
#pragma unroll
            for (int bt = 0; bt < 2; ++bt) {
                int r = wn * 32 + bt * 16 + ((lane >> 4) << 3) + (lane & 7);
                int cb = ks * 2 + ((lane >> 3) & 1);
                ldsm4(smB + r * 128 + ((cb       ^ (r & 7)) << 4), bh[bt]);
                ldsm4(smB + r * 128 + (((4 + cb) ^ (r & 7)) << 4), bl[bt]);
            }
#pragma unroll
            for (int mt = 0; mt < 4; ++mt) {
#pragma unroll
                for (int nt = 0; nt < 4; ++nt) {
                    const uint32_t* bhp = &bh[nt >> 1][(nt & 1) * 2];
                    const uint32_t* blp = &bl[nt >> 1][(nt & 1) * 2];
                    mma_bf16(acc[mt][nt], ah[mt], bhp[0], bhp[1]);
                    mma_bf16(acc[mt][nt], ah[mt], blp[0], blp[1]);
                    mma_bf16(acc[mt][nt], al[mt], bhp[0], bhp[1]);
                }
            }
        }
    }

    const size_t cbase = (size_t)b * MAT;

    if (mode == 2) {
        // ---- fused triu-FC epilogue
        float sc = sqrtf(norm[b]);
        float f0 = 0.f, f1 = 0.f;
#pragma unroll
        for (int mt = 0; mt < 4; ++mt) {
            int r0 = m0 + wm * 64 + mt * 16 + g;
#pragma unroll
            for (int nt = 0; nt < 4; ++nt) {
                int c0 = n0 + wn * 32 + nt * 8 + 2 * t;
                float* d = acc[mt][nt];
#pragma unroll
                for (int half = 0; half < 2; ++half) {
                    int gi = r0 + half * 8;
                    float v0 = d[half * 2 + 0] * sc;
                    float v1 = d[half * 2 + 1] * sc;
                    int tt = gi * CCH - ((gi * (gi + 1)) >> 1) + c0;
                    if (offdiag || c0 >= gi) {
                        f0 += v0 * __ldg(fcw + tt);
                        f1 += v0 * __ldg(fcw + DTRI + tt);
                    }
                    if (offdiag || c0 + 1 >= gi) {
                        f0 += v1 * __ldg(fcw + tt + 1);
                        f1 += v1 * __ldg(fcw + DTRI + tt + 1);
                    }
                }
            }
        }
        __syncthreads();
        float* red = reinterpret_cast<float*>(smem);
        red[tid] = f0; red[256 + tid] = f1;
        __syncthreads();
        for (int off = 128; off > 0; off >>= 1) {
            if (tid < off) { red[tid] += red[tid + off]; red[256 + tid] += red[256 + tid + off]; }
            __syncthreads();
        }
        if (tid == 0) {
            part[(b * 3 + bx) * 2 + 0] = red[0];
            part[(b * 3 + bx) * 2 + 1] = red[256];
        }
        return;
    }

    float invMn = 0.0f;
    const float* sb = 0;
    if (mode == 3) {
        invMn = 1.0f / (196.0f * norm[b]);
        sb = sums + b * CCH;
    }

#pragma unroll
    for (int mt = 0; mt < 4; ++mt) {
        int r0 = m0 + wm * 64 + mt * 16 + g;
#pragma unroll
        for (int nt = 0; nt < 4; ++nt) {
            int c0 = n0 + wn * 32 + nt * 8 + 2 * t;
            float* d = acc[mt][nt];
#pragma unroll
            for (int half = 0; half < 2; ++half) {
                int gi = r0 + half * 8;
                float v0 = d[half * 2 + 0];
                float v1 = d[half * 2 + 1];
                size_t off  = cbase + (size_t)gi * CCH + c0;
                size_t mo0  = cbase + (size_t)c0 * CCH + gi;
                size_t mo1  = cbase + (size_t)(c0 + 1) * CCH + gi;
                if (mode == 1) {
                    v0 = (gi == c0     ? 1.5f : 0.0f) - 0.5f * v0;
                    v1 = (gi == c0 + 1 ? 1.5f : 0.0f) - 0.5f * v1;
                } else if (mode == 3) {
                    float si = sb[gi] * (1.0f / 196.0f);
                    v0 = (v0 - si * sb[c0])     * invMn;
                    v1 = (v1 - si * sb[c0 + 1]) * invMn;
                    float w0 = (gi == c0     ? 1.5f : 0.0f) - 0.5f * v0;
                    float w1 = (gi == c0 + 1 ? 1.5f : 0.0f) - 0.5f * v1;
                    __nv_bfloat16 wh0 = __float2bfloat16(w0);
                    __nv_bfloat16 wh1 = __float2bfloat16(w1);
                    __nv_bfloat16 wl0 = __float2bfloat16(w0 - __bfloat162float(wh0));
                    __nv_bfloat16 wl1 = __float2bfloat16(w1 - __bfloat162float(wh1));
                    __nv_bfloat162 whp; whp.x = wh0; whp.y = wh1;
                    __nv_bfloat162 wlp; wlp.x = wl0; wlp.y = wl1;
                    *reinterpret_cast<__nv_bfloat162*>(C2hi + off) = whp;
                    *reinterpret_cast<__nv_bfloat162*>(C2lo + off) = wlp;
                    if (offdiag) {
                        C2hi[mo0] = wh0; C2lo[mo0] = wl0;
                        C2hi[mo1] = wh1; C2lo[mo1] = wl1;
                    }
                }
                __nv_bfloat16 h0 = __float2bfloat16(v0);
                __nv_bfloat16 h1 = __float2bfloat16(v1);
                __nv_bfloat16 l0 = __float2bfloat16(v0 - __bfloat162float(h0));
                __nv_bfloat16 l1 = __float2bfloat16(v1 - __bfloat162float(h1));
                __nv_bfloat162 hp; hp.x = h0; hp.y = h1;
                __nv_bfloat162 lp; lp.x = l0; lp.y = l1;
                *reinterpret_cast<__nv_bfloat162*>(pCh + off) = hp;
                *reinterpret_cast<__nv_bfloat162*>(pCl + off) = lp;
                if (offdiag) {
                    pCh[mo0] = h0; pCl[mo0] = l0;
                    pCh[mo1] = h1; pCl[mo1] = l1;
                }
            }
        }
    }
}

// ---------------------------------------------------------------------------
__global__ __launch_bounds__(256)
void split_x_kernel(const float* __restrict__ x,
                    __nv_bfloat16* __restrict__ xhi, __nv_bfloat16* __restrict__ xlo) {
    int row = blockIdx.x * 8 + (threadIdx.x >> 5);
    int lane = threadIdx.x & 31;
    const float* src = x + (size_t)row * MMSP;
    __nv_bfloat16* dh = xhi + (size_t)row * KPAD;
    __nv_bfloat16* dl = xlo + (size_t)row * KPAD;
#pragma unroll
    for (int m = lane; m < KPAD; m += 32) {
        float v = (m < MMSP) ? src[m] : 0.f;
        __nv_bfloat16 h = __float2bfloat16(v);
        dh[m] = h;
        dl[m] = __float2bfloat16(v - __bfloat162float(h));
    }
}

__global__ void rowsum_norm_kernel(const float* __restrict__ x,
                                   float* __restrict__ s, float* __restrict__ nrm) {
    int b = blockIdx.x, c = threadIdx.x;
    const float* p = x + ((size_t)b * CCH + c) * MMSP;
    float sum = 0.f, q = 0.f;
#pragma unroll 4
    for (int m = 0; m < MMSP; ++m) { float v = p[m]; sum += v; q += v * v; }
    s[b * CCH + c] = sum;
    float part = q - sum * sum * (1.0f / 196.0f);
    __shared__ float sh[8];
#pragma unroll
    for (int o = 16; o > 0; o >>= 1) part += __shfl_down_sync(0xffffffffu, part, o);
    if ((c & 31) == 0) sh[c >> 5] = part;
    __syncthreads();
    if (c < 8) {
        float w = sh[c];
#pragma unroll
        for (int o = 4; o > 0; o >>= 1) w += __shfl_down_sync(0xffu, w, o);
        if (c == 0) nrm[b] = w * (1.0f / 196.0f);
    }
}

// out[b,k] = bias[k] + sum over 3 block partials
__global__ void finish_kernel(const float* __restrict__ part,
                              const float* __restrict__ bias, float* __restrict__ out) {
    int i = blockIdx.x * blockDim.x + threadIdx.x;   // 512
    int b = i >> 1, k = i & 1;
    out[i] = bias[k] + part[(b * 3 + 0) * 2 + k]
                     + part[(b * 3 + 1) * 2 + k]
                     + part[(b * 3 + 2) * 2 + k];
}

// ---------------------------------------------------------------------------
extern "C" void kernel_launch(void* const* d_in, const int* in_sizes, int n_in,
                              void* d_out, int out_size) {
    const float* x    = (const float*)d_in[0];
    const float* fc_w = (const float*)d_in[1];
    const float* fc_b = (const float*)d_in[2];
    float* out        = (float*)d_out;

    __nv_bfloat16 *Xh, *Xl, *Ph, *Pl, *Qh, *Ql, *Rh, *Rl, *Sh, *Sl, *Th, *Tl;
    float *part, *sums, *nrm;
    cudaGetSymbolAddress((void**)&Xh, g_Xhi); cudaGetSymbolAddress((void**)&Xl, g_Xlo);
    cudaGetSymbolAddress((void**)&Ph, g_Phi); cudaGetSymbolAddress((void**)&Pl, g_Plo);
    cudaGetSymbolAddress((void**)&Qh, g_Qhi); cudaGetSymbolAddress((void**)&Ql, g_Qlo);
    cudaGetSymbolAddress((void**)&Rh, g_Rhi); cudaGetSymbolAddress((void**)&Rl, g_Rlo);
    cudaGetSymbolAddress((void**)&Sh, g_Shi); cudaGetSymbolAddress((void**)&Sl, g_Slo);
    cudaGetSymbolAddress((void**)&Th, g_Thi); cudaGetSymbolAddress((void**)&Tl, g_Tlo);
    cudaGetSymbolAddress((void**)&part, g_part);
    cudaGetSymbolAddress((void**)&sums, g_sums);
    cudaGetSymbolAddress((void**)&nrm, g_norm);

    cudaFuncSetAttribute(gemm_tc, cudaFuncAttributeMaxDynamicSharedMemorySize, SMEM_TOTAL);

    dim3 g1(3, BATCH);   // single symmetric GEMM
    dim3 g2(6, BATCH);   // fused pair
    const long strX = (long)CCH * KPAD;
    const long strM = (long)MAT;
    const __nv_bfloat16* nbp = 0;
    __nv_bfloat16* nbo = 0;

    rowsum_norm_kernel<<<BATCH, CCH>>>(x, sums, nrm);
    split_x_kernel<<<BATCH * CCH / 8, 256>>>(x, Xh, Xl);

    // cov+hat: P=Ahat, Q=ZY
    gemm_tc<<<g1, 256, SMEM_TOTAL>>>(Xh, Xl, Xh, Xl, Ph, Pl, Qh, Ql,
                                     nbp, nbp, nbp, nbp, nbo, nbo, (const float*)0, (float*)0,
                                     KPAD, strX, KPAD, 3, nrm, sums);
    // Y0: R = P@Q
    gemm_tc<<<g1, 256, SMEM_TOTAL>>>(Ph, Pl, Qh, Ql, Rh, Rl, nbo, nbo,
                                     nbp, nbp, nbp, nbp, nbo, nbo, (const float*)0, (float*)0,
                                     CCH, strM, CCH, 0, nrm, 0);
    // T1: S = TI(Q@R)
    gemm_tc<<<g1, 256, SMEM_TOTAL>>>(Qh, Ql, Rh, Rl, Sh, Sl, nbo, nbo,
                                     nbp, nbp, nbp, nbp, nbo, nbo, (const float*)0, (float*)0,
                                     CCH, strM, CCH, 1, nrm, 0);
    // pair1: T = R@S (Y1), P = S@Q (Z1)
    gemm_tc<<<g2, 256, SMEM_TOTAL>>>(Rh, Rl, Sh, Sl, Th, Tl, nbo, nbo,
                                     Sh, Sl, Qh, Ql, Ph, Pl, (const float*)0, (float*)0,
                                     CCH, strM, CCH, 0, nrm, 0);
    // T2: S = TI(P@T)
    gemm_tc<<<g1, 256, SMEM_TOTAL>>>(Ph, Pl, Th, Tl, Sh, Sl, nbo, nbo,
                                     nbp, nbp, nbp, nbp, nbo, nbo, (const float*)0, (float*)0,
                                     CCH, strM, CCH, 1, nrm, 0);
    // pair2: Q = T@S (Y2), R = S@P (Z2)
    gemm_tc<<<g2, 256, SMEM_TOTAL>>>(Th, Tl, Sh, Sl, Qh, Ql, nbo, nbo,
                                     Sh, Sl, Ph, Pl, Rh, Rl, (const float*)0, (float*)0,
                                     CCH, strM, CCH, 0, nrm, 0);
    // T3: S = TI(R@Q)
    gemm_tc<<<g1, 256, SMEM_TOTAL>>>(Rh, Rl, Qh, Ql, Sh, Sl, nbo, nbo,
                                     nbp, nbp, nbp, nbp, nbo, nbo, (const float*)0, (float*)0,
                                     CCH, strM, CCH, 1, nrm, 0);
    // pair3: T = Q@S (Y3), P = S@R (Z3)
    gemm_tc<<<g2, 256, SMEM_TOTAL>>>(Qh, Ql, Sh, Sl, Th, Tl, nbo, nbo,
                                     Sh, Sl, Rh, Rl, Ph, Pl, (const float*)0, (float*)0,
                                     CCH, strM, CCH, 0, nrm, 0);
    // T4: S = TI(P@T)
    gemm_tc<<<g1, 256, SMEM_TOTAL>>>(Ph, Pl, Th, Tl, Sh, Sl, nbo, nbo,
                                     nbp, nbp, nbp, nbp, nbo, nbo, (const float*)0, (float*)0,
                                     CCH, strM, CCH, 1, nrm, 0);
    // final: fused triu-FC on (T@S)*sqrt(norm)
    gemm_tc<<<g1, 256, SMEM_TOTAL>>>(Th, Tl, Sh, Sl, nbo, nbo, nbo, nbo,
                                     nbp, nbp, nbp, nbp, nbo, nbo, fc_w, part,
                                     CCH, strM, CCH, 2, nrm, 0);

    finish_kernel<<<2, 256>>>(part, fc_b, out);
}